// round 1
// baseline (speedup 1.0000x reference)
#include <cuda_runtime.h>

// Problem dims (fixed by the dataset)
#define Bsz   2
#define Hn    16
#define BHn   32          // B*H
#define Qlen  2048
#define Slen  2048
#define Dd    64
#define QS    (Qlen * Slen)          // 4,194,304 per (b,h)
#define NROWS (BHn * Qlen)           // 65,536 softmax rows

// Softmax row statistics scratch (sanctioned __device__ globals, 512 KB)
__device__ float g_rowmax[NROWS];
__device__ float g_rowinv[NROWS];

__device__ __forceinline__ float neg_inf_f() { return __int_as_float(0xff800000); }

// ---------------------------------------------------------------------------
// Kernel 1: scores = q @ k * scale + prev + mask  (+ key padding -> -inf)
// Tile: 128 (q) x 64 (s), K = D = 64 in one shot.
// ---------------------------------------------------------------------------
__global__ __launch_bounds__(256) void k1_scores(
    const float* __restrict__ Qp, const float* __restrict__ Kp,
    const float* __restrict__ Pp, const float* __restrict__ Mp,
    const unsigned char* __restrict__ KPM, const float* __restrict__ Sc,
    float* __restrict__ OutS)
{
    __shared__ float Qs[128][64];   // column-swizzled by bit3 of row
    __shared__ float Ks[64][64];    // natural [d][s]

    const int tid = threadIdx.x;
    const int bh  = blockIdx.z;
    const int q0  = blockIdx.y * 128;
    const int s0  = blockIdx.x * 64;
    const int b   = bh >> 4;        // H = 16
    const float scale = *Sc;

    // Load Q tile: rows q0..q0+127, fully contiguous 8192 floats.
    {
        const float4* src = (const float4*)(Qp + (size_t)(bh * Qlen + q0) * Dd);
        #pragma unroll
        for (int i = 0; i < 8; ++i) {
            int j  = tid + i * 256;
            int m  = j >> 4;
            int c4 = j & 15;
            float4 x = src[j];
            int col = (c4 * 4) ^ (((m >> 3) & 1) << 4);   // XOR-16 swizzle
            *(float4*)&Qs[m][col] = x;
        }
    }
    // Load K tile: k is [B,H,D,S]; row d at stride Slen.
    {
        #pragma unroll
        for (int i = 0; i < 4; ++i) {
            int j  = tid + i * 256;
            int d  = j >> 4;
            int c4 = j & 15;
            float4 x = *(const float4*)(Kp + (size_t)(bh * Dd + d) * Slen + s0 + c4 * 4);
            *(float4*)&Ks[d][c4 * 4] = x;
        }
    }
    __syncthreads();

    const int tx = tid & 15;        // column group: 4 cols each -> 64
    const int ty = tid >> 4;        // row group: 8 rows each -> 128
    const int sw = (ty & 1) << 4;   // matches store swizzle: (m>>3)&1 == ty

    float acc[8][4] = {};

    #pragma unroll 8
    for (int kd = 0; kd < 64; ++kd) {
        float4 bv = *(const float4*)&Ks[kd][tx * 4];
        float a[8];
        #pragma unroll
        for (int i = 0; i < 8; ++i) a[i] = Qs[ty * 8 + i][kd ^ sw];
        #pragma unroll
        for (int i = 0; i < 8; ++i) {
            acc[i][0] += a[i] * bv.x;
            acc[i][1] += a[i] * bv.y;
            acc[i][2] += a[i] * bv.z;
            acc[i][3] += a[i] * bv.w;
        }
    }

    // Epilogue: scale, + prev, + mask, key padding, store.
    uchar4 kp = *(const uchar4*)(KPM + b * Slen + s0 + tx * 4);
    #pragma unroll
    for (int i = 0; i < 8; ++i) {
        int qg = q0 + ty * 8 + i;
        size_t off  = (size_t)bh * QS + (size_t)qg * Slen + s0 + tx * 4;
        size_t moff = (size_t)qg * Slen + s0 + tx * 4;
        float4 pv = *(const float4*)(Pp + off);
        float4 mv = *(const float4*)(Mp + moff);
        float4 r;
        r.x = acc[i][0] * scale + pv.x + mv.x;
        r.y = acc[i][1] * scale + pv.y + mv.y;
        r.z = acc[i][2] * scale + pv.z + mv.z;
        r.w = acc[i][3] * scale + pv.w + mv.w;
        if (kp.x) r.x = neg_inf_f();
        if (kp.y) r.y = neg_inf_f();
        if (kp.z) r.z = neg_inf_f();
        if (kp.w) r.w = neg_inf_f();
        *(float4*)(OutS + off) = r;
    }
}

// ---------------------------------------------------------------------------
// Kernel 2: per-row max and 1/sum(exp(s - max)). One CTA (256 thr) per row.
// Row data held in registers: single DRAM read of scores.
// ---------------------------------------------------------------------------
__global__ __launch_bounds__(256) void k2_stats(const float* __restrict__ S)
{
    const int r   = blockIdx.x;
    const int tid = threadIdx.x;
    const float4* row = (const float4*)(S + (size_t)r * Slen);
    float4 v0 = row[tid];
    float4 v1 = row[tid + 256];

    float m = fmaxf(fmaxf(fmaxf(v0.x, v0.y), fmaxf(v0.z, v0.w)),
                    fmaxf(fmaxf(v1.x, v1.y), fmaxf(v1.z, v1.w)));
    #pragma unroll
    for (int o = 16; o; o >>= 1) m = fmaxf(m, __shfl_xor_sync(0xffffffffu, m, o));

    __shared__ float red[8];
    const int w = tid >> 5, l = tid & 31;
    if (l == 0) red[w] = m;
    __syncthreads();
    float M = red[0];
    #pragma unroll
    for (int i = 1; i < 8; ++i) M = fmaxf(M, red[i]);
    __syncthreads();   // before reusing red[]

    float s = __expf(v0.x - M) + __expf(v0.y - M) + __expf(v0.z - M) + __expf(v0.w - M)
            + __expf(v1.x - M) + __expf(v1.y - M) + __expf(v1.z - M) + __expf(v1.w - M);
    #pragma unroll
    for (int o = 16; o; o >>= 1) s += __shfl_xor_sync(0xffffffffu, s, o);
    if (l == 0) red[w] = s;
    __syncthreads();
    if (tid == 0) {
        float t = red[0] + red[1] + red[2] + red[3] + red[4] + red[5] + red[6] + red[7];
        g_rowmax[r] = M;
        g_rowinv[r] = 1.0f / t;
    }
}

// ---------------------------------------------------------------------------
// Kernel 3: attn = exp(scores - max) * inv_sum (written to gmem once),
//           out  = attn @ v  accumulated in the same pass.
// Tile: 64 (q) x 64 (d = full headdim), looping S in chunks of 64.
// ---------------------------------------------------------------------------
__global__ __launch_bounds__(256) void k3_out(
    const float* __restrict__ S, const float* __restrict__ V,
    float* __restrict__ A, float* __restrict__ O)
{
    __shared__ float Ps[64][64];    // column-swizzled by bit2 of row
    __shared__ float Vs[64][64];    // natural [s][d]

    const int tid = threadIdx.x;
    const int bh  = blockIdx.y;
    const int q0  = blockIdx.x * 64;
    const int tx  = tid & 15;
    const int ty  = tid >> 4;
    const int sw  = (ty & 1) << 4;  // matches store swizzle: (m>>2)&1 == ty

    // Per-thread loading rows are qr = (tid>>4) + 16*i : cache their stats.
    float Mr[4], Ir[4];
    #pragma unroll
    for (int i = 0; i < 4; ++i) {
        int r = bh * Qlen + q0 + (tid >> 4) + i * 16;
        Mr[i] = g_rowmax[r];
        Ir[i] = g_rowinv[r];
    }

    float acc[4][4] = {};

    for (int st = 0; st < 32; ++st) {
        const int s0 = st * 64;
        // Load scores tile, apply softmax, write attn, stage P in smem.
        #pragma unroll
        for (int i = 0; i < 4; ++i) {
            int j  = tid + i * 256;
            int qr = j >> 4;
            int c4 = j & 15;
            size_t off = (size_t)bh * QS + (size_t)(q0 + qr) * Slen + s0 + c4 * 4;
            float4 x = *(const float4*)(S + off);
            float4 p;
            p.x = __expf(x.x - Mr[i]) * Ir[i];
            p.y = __expf(x.y - Mr[i]) * Ir[i];
            p.z = __expf(x.z - Mr[i]) * Ir[i];
            p.w = __expf(x.w - Mr[i]) * Ir[i];
            *(float4*)(A + off) = p;
            int col = (c4 * 4) ^ (((qr >> 2) & 1) << 4);
            *(float4*)&Ps[qr][col] = p;
        }
        // Load V tile: rows s0..s0+63, fully contiguous 4096 floats.
        {
            const float4* vsrc = (const float4*)(V + (size_t)(bh * Slen + s0) * Dd);
            #pragma unroll
            for (int i = 0; i < 4; ++i) {
                int j  = tid + i * 256;
                int sr = j >> 4;
                int c4 = j & 15;
                *(float4*)&Vs[sr][c4 * 4] = vsrc[j];
            }
        }
        __syncthreads();

        #pragma unroll 8
        for (int kd = 0; kd < 64; ++kd) {
            float4 bv = *(const float4*)&Vs[kd][tx * 4];
            float a[4];
            #pragma unroll
            for (int i = 0; i < 4; ++i) a[i] = Ps[ty * 4 + i][kd ^ sw];
            #pragma unroll
            for (int i = 0; i < 4; ++i) {
                acc[i][0] += a[i] * bv.x;
                acc[i][1] += a[i] * bv.y;
                acc[i][2] += a[i] * bv.z;
                acc[i][3] += a[i] * bv.w;
            }
        }
        __syncthreads();
    }

    #pragma unroll
    for (int i = 0; i < 4; ++i) {
        int qg = q0 + ty * 4 + i;
        float4 r;
        r.x = acc[i][0]; r.y = acc[i][1]; r.z = acc[i][2]; r.w = acc[i][3];
        *(float4*)(O + (size_t)(bh * Qlen + qg) * Dd + tx * 4) = r;
    }
}

// ---------------------------------------------------------------------------
// Launch: d_out = [ out (B,H,Q,D) | attn (B,H,Q,S) | scores (B,H,Q,S) ]
// ---------------------------------------------------------------------------
extern "C" void kernel_launch(void* const* d_in, const int* in_sizes, int n_in,
                              void* d_out, int out_size)
{
    const float*         q     = (const float*)d_in[0];
    const float*         k     = (const float*)d_in[1];
    const float*         v     = (const float*)d_in[2];
    const float*         scale = (const float*)d_in[3];
    const float*         prev  = (const float*)d_in[4];
    const float*         mask  = (const float*)d_in[5];
    const unsigned char* kpm   = (const unsigned char*)d_in[6];
    // d_in[7] = cross (==0, ignored: non-cross branch)

    float* out    = (float*)d_out;
    float* attn   = out  + (size_t)BHn * Qlen * Dd;
    float* scores = attn + (size_t)BHn * QS;

    k1_scores<<<dim3(Slen / 64, Qlen / 128, BHn), 256>>>(q, k, prev, mask, kpm, scale, scores);
    k2_stats<<<NROWS, 256>>>(scores);
    k3_out<<<dim3(Qlen / 64, BHn), 256>>>(scores, v, attn, out);
}